// round 12
// baseline (speedup 1.0000x reference)
#include <cuda_runtime.h>
#include <cstdint>

#define T_SEQ  512
#define NBATCH 128
#define DIN    256
#define DH     1024
#define NRANK  128
#define DOUT   256
#define BDH    (NBATCH * DH)
#define NGRP   2          // batch groups per cluster
#define NCLUS  8          // clusters

// ---------------- scratch ---------------------------------------------------------
__device__ float g_zi[(size_t)T_SEQ * NBATCH * DH];
__device__ float g_hidden_scratch[(size_t)T_SEQ * NBATCH * DH];
__device__ float g_Ppart[2 * NCLUS * 8 * 2048];  // [parity][cluster][bin8][G*1024+r*8+b]

// ---------------- helpers ---------------------------------------------------------
__device__ __forceinline__ unsigned f2tf(float x)
{
    unsigned r;
    asm("cvt.rna.tf32.f32 %0, %1;" : "=r"(r) : "f"(x));
    return r;
}

__device__ __forceinline__ void mma_tf32(float c[4],
                                         unsigned a0, unsigned a1, unsigned a2, unsigned a3,
                                         unsigned b0, unsigned b1)
{
    asm volatile(
        "mma.sync.aligned.m16n8k8.row.col.f32.tf32.tf32.f32 "
        "{%0,%1,%2,%3}, {%4,%5,%6,%7}, {%8,%9}, {%0,%1,%2,%3};"
        : "+f"(c[0]), "+f"(c[1]), "+f"(c[2]), "+f"(c[3])
        : "r"(a0), "r"(a1), "r"(a2), "r"(a3), "r"(b0), "r"(b1));
}

__device__ __forceinline__ void cluster_sync()
{
    asm volatile("barrier.cluster.arrive.aligned;" ::: "memory");
    asm volatile("barrier.cluster.wait.aligned;" ::: "memory");
}

// ---------------- persistent recurrence kernel ------------------------------------
// 8 clusters x 8 CTAs; cluster gg owns batches [16gg, 16gg+16) as 2 groups of 8.
// CTA c owns DH-slice [128c,128c+128) as BOTH stage2 j-slice and stage1 k-slice.
// Warp (kh = w>>2, wq = w&3): 32 output rows [32wq,32wq+32) over K-half kh.
// BALANCED halves (bit-identical to R10 math): each warp computes both groups'
// partials over its K-half, cross-writes group (1-kh) to smem `red`, and
// FINALIZES group kh (bin store / epilogue). Symmetric tail at every barrier.
// smem (words): ufrag 16384 | vfrag 16384 | hst 2048 | pst 2048 | red 2048
#define RSM_WORDS (16384 + 16384 + 2048 + 2048 + 2048)
#define RSM_BYTES (RSM_WORDS * 4)

__global__ void __cluster_dims__(8, 1, 1) __launch_bounds__(256, 1)
rnn_rec_tf32(const float* __restrict__ U, const float* __restrict__ V,
             const float* __restrict__ bh, const float* __restrict__ zi,
             float* __restrict__ hidden, float* __restrict__ ppart)
{
    extern __shared__ unsigned sm[];
    unsigned* ufrag = sm;
    unsigned* vfrag = sm + 16384;
    unsigned* hst   = sm + 32768;          // [G][k*8 + b]
    unsigned* pst   = sm + 32768 + 2048;   // [G][r*8 + b]
    float*    red   = (float*)(sm + 32768 + 4096);  // [G][x*8 + b] scratch

    const int tid  = threadIdx.x;
    const int w    = tid >> 5;
    const int lane = tid & 31;
    const int grp  = lane >> 2;
    const int qid  = lane & 3;
    const int kh   = w >> 2;     // K-half AND finalized group
    const int wq   = w & 3;      // 32-row tile

    const int c   = blockIdx.x & 7;
    const int gg  = blockIdx.x >> 3;
    const int b0g = gg * 16;

    // ---- build ufrag: A = U[r 0..127][k_local 0..127]; frame(a=r>>4, i8=k>>3)
    #pragma unroll
    for (int it = 0; it < 16; ++it) {
        const int f  = it * 256 + tid;
        const int r  = f >> 5;
        const int kq = f & 31;
        const float4 u4 = __ldg((const float4*)(U + (size_t)r * DH + c * 128 + kq * 4));
        const int a_ = r >> 4, grp_ = r & 7, mh = (r >> 3) & 1;
        const int i8 = kq >> 1, khw = kq & 1;
        const unsigned base = (unsigned)(((a_ * 16 + i8) * 32 + grp_ * 4) * 4 + khw * 2 + mh);
        ufrag[base + 0]  = f2tf(u4.x);
        ufrag[base + 4]  = f2tf(u4.y);
        ufrag[base + 8]  = f2tf(u4.z);
        ufrag[base + 12] = f2tf(u4.w);
    }
    // ---- build vfrag: A = V[j_local 0..127][r 0..127]; frame(a=j>>4, i8=r>>3)
    #pragma unroll
    for (int it = 0; it < 16; ++it) {
        const int f  = it * 256 + tid;
        const int jl = f >> 5;
        const int rq = f & 31;
        const float4 v4 = __ldg((const float4*)(V + (size_t)(c * 128 + jl) * NRANK + rq * 4));
        const int a_ = jl >> 4, grp_ = jl & 7, mh = (jl >> 3) & 1;
        const int i8 = rq >> 1, khw = rq & 1;
        const unsigned base = (unsigned)(((a_ * 16 + i8) * 32 + grp_ * 4) * 4 + khw * 2 + mh);
        vfrag[base + 0]  = f2tf(v4.x);
        vfrag[base + 4]  = f2tf(v4.y);
        vfrag[base + 8]  = f2tf(v4.z);
        vfrag[base + 12] = f2tf(v4.w);
    }
    // ---- init h(t=-1) = 0
    #pragma unroll
    for (int it = 0; it < 8; ++it)
        hst[it * 256 + tid] = 0u;
    __syncthreads();

    // warp-local fragment bases: frames (2wq, kh*8 + i) and (2wq+1, kh*8 + i)
    const unsigned* const ufA = ufrag + (2 * wq * 16 + kh * 8) * 128 + lane * 4;
    const unsigned* const vfA = vfrag + (2 * wq * 16 + kh * 8) * 128 + lane * 4;

    float bias_[2][2];
    #pragma unroll
    for (int mh = 0; mh < 2; ++mh)
        #pragma unroll
        for (int rh = 0; rh < 2; ++rh)
            bias_[mh][rh] = __ldg(bh + c * 128 + 32 * wq + 16 * mh + grp + 8 * rh);

    for (int t = 0; t < T_SEQ; ++t) {
        // ---- zi prefetch for this warp's FINALIZED group (kh)
        float z[2][4];
        {
            const float* zit = zi + (size_t)t * BDH;
            #pragma unroll
            for (int mh = 0; mh < 2; ++mh) {
                const size_t base = (size_t)(b0g + 8 * kh + 2 * qid) * DH
                                  + c * 128 + 32 * wq + 16 * mh + grp;
                z[mh][0] = __ldg(zit + base);
                z[mh][1] = __ldg(zit + base + DH);
                z[mh][2] = __ldg(zit + base + 8);
                z[mh][3] = __ldg(zit + base + DH + 8);
            }
        }

        // ---- stage1: partial P over K-half kh; rows [32wq, 32wq+32), both groups
        float s1[NGRP][2][4];
        #pragma unroll
        for (int G = 0; G < NGRP; ++G)
            #pragma unroll
            for (int mh = 0; mh < 2; ++mh)
                #pragma unroll
                for (int j = 0; j < 4; ++j) s1[G][mh][j] = 0.f;
        #pragma unroll
        for (int i = 0; i < 8; ++i) {
            const uint4 aA = *(const uint4*)(ufA + i * 128);
            const uint4 aB = *(const uint4*)(ufA + i * 128 + 2048);
            const int kk = kh * 64 + 8 * i;
            #pragma unroll
            for (int G = 0; G < NGRP; ++G) {
                const unsigned b0 = hst[G * 1024 + (kk + qid) * 8 + grp];
                const unsigned b1 = hst[G * 1024 + (kk + qid + 4) * 8 + grp];
                mma_tf32(s1[G][0], aA.x, aA.y, aA.z, aA.w, b0, b1);
                mma_tf32(s1[G][1], aB.x, aB.y, aB.z, aB.w, b0, b1);
            }
        }
        // ---- cross-write group (1-kh) to red; finalize group kh into the bin
        {
            const int Go = 1 - kh;
            #pragma unroll
            for (int mh = 0; mh < 2; ++mh) {
                const int r_ = 32 * wq + 16 * mh + grp;
                red[Go * 1024 + r_ * 8 + 2 * qid]           = s1[Go][mh][0];
                red[Go * 1024 + r_ * 8 + 2 * qid + 1]       = s1[Go][mh][1];
                red[Go * 1024 + (r_ + 8) * 8 + 2 * qid]     = s1[Go][mh][2];
                red[Go * 1024 + (r_ + 8) * 8 + 2 * qid + 1] = s1[Go][mh][3];
            }
        }
        __syncthreads();
        {
            float* pp = ppart + (size_t)((((t & 1) * NCLUS + gg) * 8) + c) * 2048
                      + kh * 1024;
            #pragma unroll
            for (int mh = 0; mh < 2; ++mh) {
                const int r_ = 32 * wq + 16 * mh + grp;
                *(float2*)(pp + r_ * 8 + 2 * qid) = make_float2(
                    s1[kh][mh][0] + red[kh * 1024 + r_ * 8 + 2 * qid],
                    s1[kh][mh][1] + red[kh * 1024 + r_ * 8 + 2 * qid + 1]);
                *(float2*)(pp + (r_ + 8) * 8 + 2 * qid) = make_float2(
                    s1[kh][mh][2] + red[kh * 1024 + (r_ + 8) * 8 + 2 * qid],
                    s1[kh][mh][3] + red[kh * 1024 + (r_ + 8) * 8 + 2 * qid + 1]);
            }
        }
        cluster_sync();   // merged partials visible cluster-wide

        // ---- gather: sum 8 bins -> pst (tf32)
        {
            const float* gb = ppart + (size_t)((t & 1) * NCLUS + gg) * 8 * 2048;
            #pragma unroll
            for (int jj = 0; jj < 2; ++jj) {
                const int o4 = (tid + 256 * jj) * 4;
                float4 s = __ldcg((const float4*)(gb + o4));
                #pragma unroll
                for (int bb = 1; bb < 8; ++bb) {
                    const float4 q = __ldcg((const float4*)(gb + bb * 2048 + o4));
                    s.x += q.x; s.y += q.y; s.z += q.z; s.w += q.w;
                }
                uint4 d;
                d.x = f2tf(s.x); d.y = f2tf(s.y); d.z = f2tf(s.z); d.w = f2tf(s.w);
                *(uint4*)(pst + o4) = d;
            }
        }
        __syncthreads();

        // ---- stage2: h' partial over r-half kh; rows [32wq, 32wq+32), both groups
        float s2[NGRP][2][4];
        #pragma unroll
        for (int G = 0; G < NGRP; ++G)
            #pragma unroll
            for (int mh = 0; mh < 2; ++mh)
                #pragma unroll
                for (int j = 0; j < 4; ++j) s2[G][mh][j] = 0.f;
        #pragma unroll
        for (int i = 0; i < 8; ++i) {
            const uint4 aA = *(const uint4*)(vfA + i * 128);
            const uint4 aB = *(const uint4*)(vfA + i * 128 + 2048);
            const int kk = kh * 64 + 8 * i;
            #pragma unroll
            for (int G = 0; G < NGRP; ++G) {
                const unsigned b0 = pst[G * 1024 + (kk + qid) * 8 + grp];
                const unsigned b1 = pst[G * 1024 + (kk + qid + 4) * 8 + grp];
                mma_tf32(s2[G][0], aA.x, aA.y, aA.z, aA.w, b0, b1);
                mma_tf32(s2[G][1], aB.x, aB.y, aB.z, aB.w, b0, b1);
            }
        }
        // ---- cross-write group (1-kh) to red; epilogue for group kh
        {
            const int Go = 1 - kh;
            #pragma unroll
            for (int mh = 0; mh < 2; ++mh) {
                const int jl = 32 * wq + 16 * mh + grp;
                red[Go * 1024 + jl * 8 + 2 * qid]           = s2[Go][mh][0];
                red[Go * 1024 + jl * 8 + 2 * qid + 1]       = s2[Go][mh][1];
                red[Go * 1024 + (jl + 8) * 8 + 2 * qid]     = s2[Go][mh][2];
                red[Go * 1024 + (jl + 8) * 8 + 2 * qid + 1] = s2[Go][mh][3];
            }
        }
        __syncthreads();
        {
            float* ht = hidden + (size_t)t * BDH;
            #pragma unroll
            for (int mh = 0; mh < 2; ++mh) {
                const int jl = 32 * wq + 16 * mh + grp;
                const float h00 = fmaxf(s2[kh][mh][0] + red[kh * 1024 + jl * 8 + 2 * qid]
                                        + bias_[mh][0] + z[mh][0], 0.f);
                const float h01 = fmaxf(s2[kh][mh][1] + red[kh * 1024 + jl * 8 + 2 * qid + 1]
                                        + bias_[mh][0] + z[mh][1], 0.f);
                const float h10 = fmaxf(s2[kh][mh][2] + red[kh * 1024 + (jl + 8) * 8 + 2 * qid]
                                        + bias_[mh][1] + z[mh][2], 0.f);
                const float h11 = fmaxf(s2[kh][mh][3] + red[kh * 1024 + (jl + 8) * 8 + 2 * qid + 1]
                                        + bias_[mh][1] + z[mh][3], 0.f);
                const size_t base = (size_t)(b0g + 8 * kh + 2 * qid) * DH + c * 128 + jl;
                ht[base]          = h00;
                ht[base + DH]     = h01;
                ht[base + 8]      = h10;
                ht[base + DH + 8] = h11;
                hst[kh * 1024 + jl * 8 + 2 * qid]           = f2tf(h00);
                hst[kh * 1024 + jl * 8 + 2 * qid + 1]       = f2tf(h01);
                hst[kh * 1024 + (jl + 8) * 8 + 2 * qid]     = f2tf(h10);
                hst[kh * 1024 + (jl + 8) * 8 + 2 * qid + 1] = f2tf(h11);
            }
        }
        __syncthreads();  // hst ready for next step
    }
}

// ---------------- tf32 NT GEMM (swizzled scalar-LDS, RNA — R10-proven, both phases)
template <bool BIAS>
__global__ void __launch_bounds__(256, 2)
gemm_tf32_nt(const float* __restrict__ A, const float* __restrict__ B,
             const float* __restrict__ bias, float* __restrict__ C,
             int M, int N, int K)
{
    __shared__ unsigned As[2][16][136];
    __shared__ unsigned Bs[2][16][136];

    const int tid  = threadIdx.x;
    const int wid  = tid >> 5;
    const int lane = tid & 31;
    const int grp  = lane >> 2;
    const int qid  = lane & 3;
    const int wm   = (wid >> 1) * 32;
    const int wn   = (wid & 1) * 64;
    const int m0   = blockIdx.y * 128;
    const int n0   = blockIdx.x * 128;
    const int lm   = tid >> 2;
    const int lk   = (tid & 3) << 2;
    const int lk4  = tid & 3;
    const int cm0  = lm ^ (lk4 * 8);

    const float* Ap0 = A + (size_t)(m0 + lm) * K + lk;
    const float* Ap1 = Ap0 + (size_t)64 * K;
    const float* Bp0 = B + (size_t)(n0 + lm) * K + lk;
    const float* Bp1 = Bp0 + (size_t)64 * K;

    float acc[2][8][4];
    #pragma unroll
    for (int mt = 0; mt < 2; ++mt)
        #pragma unroll
        for (int nt = 0; nt < 8; ++nt)
            #pragma unroll
            for (int j = 0; j < 4; ++j) acc[mt][nt][j] = 0.f;

    auto stage = [&](int buf, const float4& a0, const float4& a1,
                     const float4& b0, const float4& b1) {
        As[buf][lk + 0][cm0]      = f2tf(a0.x);
        As[buf][lk + 1][cm0]      = f2tf(a0.y);
        As[buf][lk + 2][cm0]      = f2tf(a0.z);
        As[buf][lk + 3][cm0]      = f2tf(a0.w);
        As[buf][lk + 0][cm0 + 64] = f2tf(a1.x);
        As[buf][lk + 1][cm0 + 64] = f2tf(a1.y);
        As[buf][lk + 2][cm0 + 64] = f2tf(a1.z);
        As[buf][lk + 3][cm0 + 64] = f2tf(a1.w);
        Bs[buf][lk + 0][cm0]      = f2tf(b0.x);
        Bs[buf][lk + 1][cm0]      = f2tf(b0.y);
        Bs[buf][lk + 2][cm0]      = f2tf(b0.z);
        Bs[buf][lk + 3][cm0]      = f2tf(b0.w);
        Bs[buf][lk + 0][cm0 + 64] = f2tf(b1.x);
        Bs[buf][lk + 1][cm0 + 64] = f2tf(b1.y);
        Bs[buf][lk + 2][cm0 + 64] = f2tf(b1.z);
        Bs[buf][lk + 3][cm0 + 64] = f2tf(b1.w);
    };

    {
        float4 a0 = *(const float4*)(Ap0);
        float4 a1 = *(const float4*)(Ap1);
        float4 b0 = *(const float4*)(Bp0);
        float4 b1 = *(const float4*)(Bp1);
        stage(0, a0, a1, b0, b1);
    }
    __syncthreads();

    int p = 0;
    for (int kt = 0; kt < K; kt += 16) {
        const bool more = (kt + 16) < K;
        float4 a0, a1, b0, b1;
        if (more) {
            a0 = *(const float4*)(Ap0 + kt + 16);
            a1 = *(const float4*)(Ap1 + kt + 16);
            b0 = *(const float4*)(Bp0 + kt + 16);
            b1 = *(const float4*)(Bp1 + kt + 16);
        }
        #pragma unroll
        for (int ks = 0; ks < 2; ++ks) {
            const int kk = ks * 8;
            const int s0 = (ks == 0) ? 0  : 16;
            const int s1 = (ks == 0) ? 8  : 24;
            unsigned af[2][4], bf[8][2];
            #pragma unroll
            for (int mt = 0; mt < 2; ++mt) {
                const int mr = wm + mt * 16 + grp;
                af[mt][0] = As[p][kk + qid][mr ^ s0];
                af[mt][1] = As[p][kk + qid][(mr + 8) ^ s0];
                af[mt][2] = As[p][kk + qid + 4][mr ^ s1];
                af[mt][3] = As[p][kk + qid + 4][(mr + 8) ^ s1];
            }
            #pragma unroll
            for (int nt = 0; nt < 8; ++nt) {
                const int nc = wn + nt * 8 + grp;
                bf[nt][0] = Bs[p][kk + qid][nc ^ s0];
                bf[nt][1] = Bs[p][kk + qid + 4][nc ^ s1];
            }
            #pragma unroll
            for (int mt = 0; mt < 2; ++mt)
                #pragma unroll
                for (int nt = 0; nt < 8; ++nt)
                    mma_tf32(acc[mt][nt], af[mt][0], af[mt][1], af[mt][2], af[mt][3],
                             bf[nt][0], bf[nt][1]);
        }
        if (more) {
            __syncthreads();
            stage(p ^ 1, a0, a1, b0, b1);
            __syncthreads();
            p ^= 1;
        }
    }

    #pragma unroll
    for (int mt = 0; mt < 2; ++mt) {
        const int mr = m0 + wm + mt * 16 + grp;
        #pragma unroll
        for (int nt = 0; nt < 8; ++nt) {
            const int nc = n0 + wn + nt * 8 + 2 * qid;
            float2 b2 = make_float2(0.f, 0.f);
            if (BIAS) b2 = *(const float2*)(bias + nc);
            float2 v0, v1;
            v0.x = acc[mt][nt][0] + b2.x; v0.y = acc[mt][nt][1] + b2.y;
            v1.x = acc[mt][nt][2] + b2.x; v1.y = acc[mt][nt][3] + b2.y;
            *(float2*)(C + (size_t)mr * N + nc)       = v0;
            *(float2*)(C + (size_t)(mr + 8) * N + nc) = v1;
        }
    }
}

// ---------------- launcher --------------------------------------------------------
extern "C" void kernel_launch(void* const* d_in, const int* in_sizes, int n_in,
                              void* d_out, int out_size)
{
    const float* x     = (const float*)d_in[0];  // [T,B,DIN]
    const float* W_in  = (const float*)d_in[1];  // [DH,DIN]
    const float* U     = (const float*)d_in[2];  // [RANK,DH]
    const float* V     = (const float*)d_in[3];  // [DH,RANK]
    const float* b_h   = (const float*)d_in[4];  // [DH]
    const float* W_out = (const float*)d_in[5];  // [DOUT,DH]
    const float* b_out = (const float*)d_in[6];  // [DOUT]

    float* zi_ptr = nullptr;
    float* hscratch = nullptr;
    float* ppart = nullptr;
    cudaGetSymbolAddress((void**)&zi_ptr, g_zi);
    cudaGetSymbolAddress((void**)&hscratch, g_hidden_scratch);
    cudaGetSymbolAddress((void**)&ppart, g_Ppart);

    const size_t HID_ELEMS = (size_t)T_SEQ * NBATCH * DH;
    const size_t OUT_ELEMS = (size_t)T_SEQ * NBATCH * DOUT;

    float* hidden_ptr;
    float* out_ptr;
    bool do_output = true;
    if ((size_t)out_size >= HID_ELEMS + OUT_ELEMS) {        // (hidden, output) concat
        hidden_ptr = (float*)d_out;
        out_ptr    = (float*)d_out + HID_ELEMS;
    } else if ((size_t)out_size == HID_ELEMS) {             // hidden only
        hidden_ptr = (float*)d_out;
        out_ptr    = nullptr;
        do_output  = false;
    } else {                                                // output only
        hidden_ptr = hscratch;
        out_ptr    = (float*)d_out;
    }

    cudaFuncSetAttribute(rnn_rec_tf32,
                         cudaFuncAttributeMaxDynamicSharedMemorySize, RSM_BYTES);

    const int M = T_SEQ * NBATCH;  // 65536

    // phase 1: zi = x @ W_in^T
    {
        dim3 grid(DH / 128, M / 128);
        gemm_tf32_nt<false><<<grid, 256>>>(x, W_in, nullptr, zi_ptr, M, DH, DIN);
    }
    // phase 2: recurrence (8 clusters x 8 CTAs, balanced kh halves)
    rnn_rec_tf32<<<NCLUS * 8, 256, RSM_BYTES>>>(U, V, b_h, zi_ptr, hidden_ptr, ppart);

    // phase 3: output = hidden @ W_out^T + b_out (R10-proven RNA GEMM)
    if (do_output) {
        dim3 grid(DOUT / 128, M / 128);
        gemm_tf32_nt<true><<<grid, 256>>>(hidden_ptr, W_out, b_out, out_ptr, M, DOUT, DH);
    }
}

// round 13
// speedup vs baseline: 1.2901x; 1.2901x over previous
#include <cuda_runtime.h>
#include <cstdint>

#define T_SEQ  512
#define NBATCH 128
#define DIN    256
#define DH     1024
#define NRANK  128
#define DOUT   256
#define BDH    (NBATCH * DH)
#define NGRP   2          // batch groups per cluster
#define NCLUS  8          // clusters

// ---------------- scratch ---------------------------------------------------------
__device__ float g_zi[(size_t)T_SEQ * NBATCH * DH];
__device__ float g_hidden_scratch[(size_t)T_SEQ * NBATCH * DH];
__device__ float g_Ppart[2 * NCLUS * 8 * 2048];  // [parity][cluster][bin8][G*1024+r*8+b]

// ---------------- helpers ---------------------------------------------------------
__device__ __forceinline__ unsigned f2tf(float x)
{
    unsigned r;
    asm("cvt.rna.tf32.f32 %0, %1;" : "=r"(r) : "f"(x));
    return r;
}

__device__ __forceinline__ void mma_tf32(float c[4],
                                         unsigned a0, unsigned a1, unsigned a2, unsigned a3,
                                         unsigned b0, unsigned b1)
{
    asm volatile(
        "mma.sync.aligned.m16n8k8.row.col.f32.tf32.tf32.f32 "
        "{%0,%1,%2,%3}, {%4,%5,%6,%7}, {%8,%9}, {%0,%1,%2,%3};"
        : "+f"(c[0]), "+f"(c[1]), "+f"(c[2]), "+f"(c[3])
        : "r"(a0), "r"(a1), "r"(a2), "r"(a3), "r"(b0), "r"(b1));
}

__device__ __forceinline__ void cluster_sync()
{
    asm volatile("barrier.cluster.arrive.aligned;" ::: "memory");
    asm volatile("barrier.cluster.wait.aligned;" ::: "memory");
}

__device__ __forceinline__ void bar_named(int id)
{
    asm volatile("bar.sync %0, 64;" :: "r"(id) : "memory");
}

// ---------------- persistent recurrence kernel ------------------------------------
// 8 clusters x 8 CTAs; cluster gg owns batches [16gg, 16gg+16) as 2 groups of 8.
// CTA c owns DH-slice [128c,128c+128) as BOTH stage2 j-slice and stage1 k-slice.
// Warp (kh = w>>2, wq = w&3): 32 output rows [32wq,32wq+32) over K-half kh.
// Stage1 kh-halves merged through smem `red` before the gmem store (8 bins).
// R13: the two PAIRWISE merges (kh1 -> kh0, same wq) use 64-thread named
// barriers (ids 1..4) instead of full __syncthreads -> less skew per step.
// smem (words): ufrag 16384 | vfrag 16384 | hst 2048 | pst 2048 | red 2048
#define RSM_WORDS (16384 + 16384 + 2048 + 2048 + 2048)
#define RSM_BYTES (RSM_WORDS * 4)

__global__ void __cluster_dims__(8, 1, 1) __launch_bounds__(256, 1)
rnn_rec_tf32(const float* __restrict__ U, const float* __restrict__ V,
             const float* __restrict__ bh, const float* __restrict__ zi,
             float* __restrict__ hidden, float* __restrict__ ppart)
{
    extern __shared__ unsigned sm[];
    unsigned* ufrag = sm;
    unsigned* vfrag = sm + 16384;
    unsigned* hst   = sm + 32768;          // [G][k*8 + b]
    unsigned* pst   = sm + 32768 + 2048;   // [G][r*8 + b]
    float*    red   = (float*)(sm + 32768 + 4096);  // [G][x*8 + b] scratch

    const int tid  = threadIdx.x;
    const int w    = tid >> 5;
    const int lane = tid & 31;
    const int grp  = lane >> 2;
    const int qid  = lane & 3;
    const int kh   = w >> 2;     // K-half
    const int wq   = w & 3;      // 32-row tile

    const int c   = blockIdx.x & 7;
    const int gg  = blockIdx.x >> 3;
    const int b0g = gg * 16;

    // ---- build ufrag: A = U[r 0..127][k_local 0..127]; frame(a=r>>4, i8=k>>3)
    #pragma unroll
    for (int it = 0; it < 16; ++it) {
        const int f  = it * 256 + tid;
        const int r  = f >> 5;
        const int kq = f & 31;
        const float4 u4 = __ldg((const float4*)(U + (size_t)r * DH + c * 128 + kq * 4));
        const int a_ = r >> 4, grp_ = r & 7, mh = (r >> 3) & 1;
        const int i8 = kq >> 1, khw = kq & 1;
        const unsigned base = (unsigned)(((a_ * 16 + i8) * 32 + grp_ * 4) * 4 + khw * 2 + mh);
        ufrag[base + 0]  = f2tf(u4.x);
        ufrag[base + 4]  = f2tf(u4.y);
        ufrag[base + 8]  = f2tf(u4.z);
        ufrag[base + 12] = f2tf(u4.w);
    }
    // ---- build vfrag: A = V[j_local 0..127][r 0..127]; frame(a=j>>4, i8=r>>3)
    #pragma unroll
    for (int it = 0; it < 16; ++it) {
        const int f  = it * 256 + tid;
        const int jl = f >> 5;
        const int rq = f & 31;
        const float4 v4 = __ldg((const float4*)(V + (size_t)(c * 128 + jl) * NRANK + rq * 4));
        const int a_ = jl >> 4, grp_ = jl & 7, mh = (jl >> 3) & 1;
        const int i8 = rq >> 1, khw = rq & 1;
        const unsigned base = (unsigned)(((a_ * 16 + i8) * 32 + grp_ * 4) * 4 + khw * 2 + mh);
        vfrag[base + 0]  = f2tf(v4.x);
        vfrag[base + 4]  = f2tf(v4.y);
        vfrag[base + 8]  = f2tf(v4.z);
        vfrag[base + 12] = f2tf(v4.w);
    }
    // ---- init h(t=-1) = 0
    #pragma unroll
    for (int it = 0; it < 8; ++it)
        hst[it * 256 + tid] = 0u;
    __syncthreads();

    // warp-local fragment bases: frames (2wq, kh*8 + i) and (2wq+1, kh*8 + i)
    const unsigned* const ufA = ufrag + (2 * wq * 16 + kh * 8) * 128 + lane * 4;
    const unsigned* const vfA = vfrag + (2 * wq * 16 + kh * 8) * 128 + lane * 4;

    // epilogue constants (kh==0 warps)
    float bias_[2][2];
    #pragma unroll
    for (int mh = 0; mh < 2; ++mh)
        #pragma unroll
        for (int rh = 0; rh < 2; ++rh)
            bias_[mh][rh] = __ldg(bh + c * 128 + 32 * wq + 16 * mh + grp + 8 * rh);

    for (int t = 0; t < T_SEQ; ++t) {
        // ---- zi prefetch (kh==0 warps only; consumed at epilogue)
        float z[NGRP][2][4];
        if (kh == 0) {
            const float* zit = zi + (size_t)t * BDH;
            #pragma unroll
            for (int G = 0; G < NGRP; ++G)
                #pragma unroll
                for (int mh = 0; mh < 2; ++mh) {
                    const size_t base = (size_t)(b0g + 8 * G + 2 * qid) * DH
                                      + c * 128 + 32 * wq + 16 * mh + grp;
                    z[G][mh][0] = __ldg(zit + base);
                    z[G][mh][1] = __ldg(zit + base + DH);
                    z[G][mh][2] = __ldg(zit + base + 8);
                    z[G][mh][3] = __ldg(zit + base + DH + 8);
                }
        }

        // ---- stage1: partial P over K-half kh; rows [32wq, 32wq+32)
        float s1[NGRP][2][4];
        #pragma unroll
        for (int G = 0; G < NGRP; ++G)
            #pragma unroll
            for (int mh = 0; mh < 2; ++mh)
                #pragma unroll
                for (int j = 0; j < 4; ++j) s1[G][mh][j] = 0.f;
        #pragma unroll
        for (int i = 0; i < 8; ++i) {
            const uint4 aA = *(const uint4*)(ufA + i * 128);
            const uint4 aB = *(const uint4*)(ufA + i * 128 + 2048);
            const int kk = kh * 64 + 8 * i;
            #pragma unroll
            for (int G = 0; G < NGRP; ++G) {
                const unsigned b0 = hst[G * 1024 + (kk + qid) * 8 + grp];
                const unsigned b1 = hst[G * 1024 + (kk + qid + 4) * 8 + grp];
                mma_tf32(s1[G][0], aA.x, aA.y, aA.z, aA.w, b0, b1);
                mma_tf32(s1[G][1], aB.x, aB.y, aB.z, aB.w, b0, b1);
            }
        }
        // ---- merge kh-halves through red (pairwise: kh1 -> kh0, same wq)
        if (kh == 1) {
            #pragma unroll
            for (int G = 0; G < NGRP; ++G)
                #pragma unroll
                for (int mh = 0; mh < 2; ++mh) {
                    const int r_ = 32 * wq + 16 * mh + grp;
                    red[G * 1024 + r_ * 8 + 2 * qid]           = s1[G][mh][0];
                    red[G * 1024 + r_ * 8 + 2 * qid + 1]       = s1[G][mh][1];
                    red[G * 1024 + (r_ + 8) * 8 + 2 * qid]     = s1[G][mh][2];
                    red[G * 1024 + (r_ + 8) * 8 + 2 * qid + 1] = s1[G][mh][3];
                }
        }
        bar_named(1 + wq);   // 64-thread pair barrier (warps (0,wq) and (1,wq))
        if (kh == 0) {
            float* pp = ppart + (size_t)((((t & 1) * NCLUS + gg) * 8) + c) * 2048;
            #pragma unroll
            for (int G = 0; G < NGRP; ++G)
                #pragma unroll
                for (int mh = 0; mh < 2; ++mh) {
                    const int r_ = 32 * wq + 16 * mh + grp;
                    *(float2*)(pp + G * 1024 + r_ * 8 + 2 * qid) = make_float2(
                        s1[G][mh][0] + red[G * 1024 + r_ * 8 + 2 * qid],
                        s1[G][mh][1] + red[G * 1024 + r_ * 8 + 2 * qid + 1]);
                    *(float2*)(pp + G * 1024 + (r_ + 8) * 8 + 2 * qid) = make_float2(
                        s1[G][mh][2] + red[G * 1024 + (r_ + 8) * 8 + 2 * qid],
                        s1[G][mh][3] + red[G * 1024 + (r_ + 8) * 8 + 2 * qid + 1]);
                }
        }
        cluster_sync();   // merged partials visible cluster-wide

        // ---- gather: sum 8 bins -> pst (tf32)
        {
            const float* gb = ppart + (size_t)((t & 1) * NCLUS + gg) * 8 * 2048;
            #pragma unroll
            for (int jj = 0; jj < 2; ++jj) {
                const int o4 = (tid + 256 * jj) * 4;
                float4 s = __ldcg((const float4*)(gb + o4));
                #pragma unroll
                for (int bb = 1; bb < 8; ++bb) {
                    const float4 q = __ldcg((const float4*)(gb + bb * 2048 + o4));
                    s.x += q.x; s.y += q.y; s.z += q.z; s.w += q.w;
                }
                uint4 d;
                d.x = f2tf(s.x); d.y = f2tf(s.y); d.z = f2tf(s.z); d.w = f2tf(s.w);
                *(uint4*)(pst + o4) = d;
            }
        }
        __syncthreads();

        // ---- stage2: h' partial over r-half kh; rows [32wq, 32wq+32)
        float s2[NGRP][2][4];
        #pragma unroll
        for (int G = 0; G < NGRP; ++G)
            #pragma unroll
            for (int mh = 0; mh < 2; ++mh)
                #pragma unroll
                for (int j = 0; j < 4; ++j) s2[G][mh][j] = 0.f;
        #pragma unroll
        for (int i = 0; i < 8; ++i) {
            const uint4 aA = *(const uint4*)(vfA + i * 128);
            const uint4 aB = *(const uint4*)(vfA + i * 128 + 2048);
            const int kk = kh * 64 + 8 * i;
            #pragma unroll
            for (int G = 0; G < NGRP; ++G) {
                const unsigned b0 = pst[G * 1024 + (kk + qid) * 8 + grp];
                const unsigned b1 = pst[G * 1024 + (kk + qid + 4) * 8 + grp];
                mma_tf32(s2[G][0], aA.x, aA.y, aA.z, aA.w, b0, b1);
                mma_tf32(s2[G][1], aB.x, aB.y, aB.z, aB.w, b0, b1);
            }
        }
        // ---- kh=1 half -> smem red (pairwise merge again)
        if (kh == 1) {
            #pragma unroll
            for (int G = 0; G < NGRP; ++G)
                #pragma unroll
                for (int mh = 0; mh < 2; ++mh) {
                    const int jl = 32 * wq + 16 * mh + grp;
                    red[G * 1024 + jl * 8 + 2 * qid]           = s2[G][mh][0];
                    red[G * 1024 + jl * 8 + 2 * qid + 1]       = s2[G][mh][1];
                    red[G * 1024 + (jl + 8) * 8 + 2 * qid]     = s2[G][mh][2];
                    red[G * 1024 + (jl + 8) * 8 + 2 * qid + 1] = s2[G][mh][3];
                }
        }
        bar_named(1 + wq);   // pair barrier
        // ---- epilogue (kh==0 warps): sum halves, + bias + zi, relu, store
        if (kh == 0) {
            float* ht = hidden + (size_t)t * BDH;
            #pragma unroll
            for (int G = 0; G < NGRP; ++G)
                #pragma unroll
                for (int mh = 0; mh < 2; ++mh) {
                    const int jl = 32 * wq + 16 * mh + grp;
                    const float h00 = fmaxf(s2[G][mh][0] + red[G * 1024 + jl * 8 + 2 * qid]
                                            + bias_[mh][0] + z[G][mh][0], 0.f);
                    const float h01 = fmaxf(s2[G][mh][1] + red[G * 1024 + jl * 8 + 2 * qid + 1]
                                            + bias_[mh][0] + z[G][mh][1], 0.f);
                    const float h10 = fmaxf(s2[G][mh][2] + red[G * 1024 + (jl + 8) * 8 + 2 * qid]
                                            + bias_[mh][1] + z[G][mh][2], 0.f);
                    const float h11 = fmaxf(s2[G][mh][3] + red[G * 1024 + (jl + 8) * 8 + 2 * qid + 1]
                                            + bias_[mh][1] + z[G][mh][3], 0.f);
                    const size_t base = (size_t)(b0g + 8 * G + 2 * qid) * DH + c * 128 + jl;
                    ht[base]          = h00;
                    ht[base + DH]     = h01;
                    ht[base + 8]      = h10;
                    ht[base + DH + 8] = h11;
                    hst[G * 1024 + jl * 8 + 2 * qid]           = f2tf(h00);
                    hst[G * 1024 + jl * 8 + 2 * qid + 1]       = f2tf(h01);
                    hst[G * 1024 + (jl + 8) * 8 + 2 * qid]     = f2tf(h10);
                    hst[G * 1024 + (jl + 8) * 8 + 2 * qid + 1] = f2tf(h11);
                }
        }
        __syncthreads();  // hst ready for next step (all warps read all of it)
    }
}

// ---------------- tf32 NT GEMM (swizzled scalar-LDS, RNA — R10-proven, both phases)
template <bool BIAS>
__global__ void __launch_bounds__(256, 2)
gemm_tf32_nt(const float* __restrict__ A, const float* __restrict__ B,
             const float* __restrict__ bias, float* __restrict__ C,
             int M, int N, int K)
{
    __shared__ unsigned As[2][16][136];
    __shared__ unsigned Bs[2][16][136];

    const int tid  = threadIdx.x;
    const int wid  = tid >> 5;
    const int lane = tid & 31;
    const int grp  = lane >> 2;
    const int qid  = lane & 3;
    const int wm   = (wid >> 1) * 32;
    const int wn   = (wid & 1) * 64;
    const int m0   = blockIdx.y * 128;
    const int n0   = blockIdx.x * 128;
    const int lm   = tid >> 2;
    const int lk   = (tid & 3) << 2;
    const int lk4  = tid & 3;
    const int cm0  = lm ^ (lk4 * 8);

    const float* Ap0 = A + (size_t)(m0 + lm) * K + lk;
    const float* Ap1 = Ap0 + (size_t)64 * K;
    const float* Bp0 = B + (size_t)(n0 + lm) * K + lk;
    const float* Bp1 = Bp0 + (size_t)64 * K;

    float acc[2][8][4];
    #pragma unroll
    for (int mt = 0; mt < 2; ++mt)
        #pragma unroll
        for (int nt = 0; nt < 8; ++nt)
            #pragma unroll
            for (int j = 0; j < 4; ++j) acc[mt][nt][j] = 0.f;

    auto stage = [&](int buf, const float4& a0, const float4& a1,
                     const float4& b0, const float4& b1) {
        As[buf][lk + 0][cm0]      = f2tf(a0.x);
        As[buf][lk + 1][cm0]      = f2tf(a0.y);
        As[buf][lk + 2][cm0]      = f2tf(a0.z);
        As[buf][lk + 3][cm0]      = f2tf(a0.w);
        As[buf][lk + 0][cm0 + 64] = f2tf(a1.x);
        As[buf][lk + 1][cm0 + 64] = f2tf(a1.y);
        As[buf][lk + 2][cm0 + 64] = f2tf(a1.z);
        As[buf][lk + 3][cm0 + 64] = f2tf(a1.w);
        Bs[buf][lk + 0][cm0]      = f2tf(b0.x);
        Bs[buf][lk + 1][cm0]      = f2tf(b0.y);
        Bs[buf][lk + 2][cm0]      = f2tf(b0.z);
        Bs[buf][lk + 3][cm0]      = f2tf(b0.w);
        Bs[buf][lk + 0][cm0 + 64] = f2tf(b1.x);
        Bs[buf][lk + 1][cm0 + 64] = f2tf(b1.y);
        Bs[buf][lk + 2][cm0 + 64] = f2tf(b1.z);
        Bs[buf][lk + 3][cm0 + 64] = f2tf(b1.w);
    };

    {
        float4 a0 = *(const float4*)(Ap0);
        float4 a1 = *(const float4*)(Ap1);
        float4 b0 = *(const float4*)(Bp0);
        float4 b1 = *(const float4*)(Bp1);
        stage(0, a0, a1, b0, b1);
    }
    __syncthreads();

    int p = 0;
    for (int kt = 0; kt < K; kt += 16) {
        const bool more = (kt + 16) < K;
        float4 a0, a1, b0, b1;
        if (more) {
            a0 = *(const float4*)(Ap0 + kt + 16);
            a1 = *(const float4*)(Ap1 + kt + 16);
            b0 = *(const float4*)(Bp0 + kt + 16);
            b1 = *(const float4*)(Bp1 + kt + 16);
        }
        #pragma unroll
        for (int ks = 0; ks < 2; ++ks) {
            const int kk = ks * 8;
            const int s0 = (ks == 0) ? 0  : 16;
            const int s1 = (ks == 0) ? 8  : 24;
            unsigned af[2][4], bf[8][2];
            #pragma unroll
            for (int mt = 0; mt < 2; ++mt) {
                const int mr = wm + mt * 16 + grp;
                af[mt][0] = As[p][kk + qid][mr ^ s0];
                af[mt][1] = As[p][kk + qid][(mr + 8) ^ s0];
                af[mt][2] = As[p][kk + qid + 4][mr ^ s1];
                af[mt][3] = As[p][kk + qid + 4][(mr + 8) ^ s1];
            }
            #pragma unroll
            for (int nt = 0; nt < 8; ++nt) {
                const int nc = wn + nt * 8 + grp;
                bf[nt][0] = Bs[p][kk + qid][nc ^ s0];
                bf[nt][1] = Bs[p][kk + qid + 4][nc ^ s1];
            }
            #pragma unroll
            for (int mt = 0; mt < 2; ++mt)
                #pragma unroll
                for (int nt = 0; nt < 8; ++nt)
                    mma_tf32(acc[mt][nt], af[mt][0], af[mt][1], af[mt][2], af[mt][3],
                             bf[nt][0], bf[nt][1]);
        }
        if (more) {
            __syncthreads();
            stage(p ^ 1, a0, a1, b0, b1);
            __syncthreads();
            p ^= 1;
        }
    }

    #pragma unroll
    for (int mt = 0; mt < 2; ++mt) {
        const int mr = m0 + wm + mt * 16 + grp;
        #pragma unroll
        for (int nt = 0; nt < 8; ++nt) {
            const int nc = n0 + wn + nt * 8 + 2 * qid;
            float2 b2 = make_float2(0.f, 0.f);
            if (BIAS) b2 = *(const float2*)(bias + nc);
            float2 v0, v1;
            v0.x = acc[mt][nt][0] + b2.x; v0.y = acc[mt][nt][1] + b2.y;
            v1.x = acc[mt][nt][2] + b2.x; v1.y = acc[mt][nt][3] + b2.y;
            *(float2*)(C + (size_t)mr * N + nc)       = v0;
            *(float2*)(C + (size_t)(mr + 8) * N + nc) = v1;
        }
    }
}

// ---------------- launcher --------------------------------------------------------
extern "C" void kernel_launch(void* const* d_in, const int* in_sizes, int n_in,
                              void* d_out, int out_size)
{
    const float* x     = (const float*)d_in[0];  // [T,B,DIN]
    const float* W_in  = (const float*)d_in[1];  // [DH,DIN]
    const float* U     = (const float*)d_in[2];  // [RANK,DH]
    const float* V     = (const float*)d_in[3];  // [DH,RANK]
    const float* b_h   = (const float*)d_in[4];  // [DH]
    const float* W_out = (const float*)d_in[5];  // [DOUT,DH]
    const float* b_out = (const float*)d_in[6];  // [DOUT]

    float* zi_ptr = nullptr;
    float* hscratch = nullptr;
    float* ppart = nullptr;
    cudaGetSymbolAddress((void**)&zi_ptr, g_zi);
    cudaGetSymbolAddress((void**)&hscratch, g_hidden_scratch);
    cudaGetSymbolAddress((void**)&ppart, g_Ppart);

    const size_t HID_ELEMS = (size_t)T_SEQ * NBATCH * DH;
    const size_t OUT_ELEMS = (size_t)T_SEQ * NBATCH * DOUT;

    float* hidden_ptr;
    float* out_ptr;
    bool do_output = true;
    if ((size_t)out_size >= HID_ELEMS + OUT_ELEMS) {        // (hidden, output) concat
        hidden_ptr = (float*)d_out;
        out_ptr    = (float*)d_out + HID_ELEMS;
    } else if ((size_t)out_size == HID_ELEMS) {             // hidden only
        hidden_ptr = (float*)d_out;
        out_ptr    = nullptr;
        do_output  = false;
    } else {                                                // output only
        hidden_ptr = hscratch;
        out_ptr    = (float*)d_out;
    }

    cudaFuncSetAttribute(rnn_rec_tf32,
                         cudaFuncAttributeMaxDynamicSharedMemorySize, RSM_BYTES);

    const int M = T_SEQ * NBATCH;  // 65536

    // phase 1: zi = x @ W_in^T
    {
        dim3 grid(DH / 128, M / 128);
        gemm_tf32_nt<false><<<grid, 256>>>(x, W_in, nullptr, zi_ptr, M, DH, DIN);
    }
    // phase 2: recurrence (R10 structure + pairwise named barriers)
    rnn_rec_tf32<<<NCLUS * 8, 256, RSM_BYTES>>>(U, V, b_h, zi_ptr, hidden_ptr, ppart);

    // phase 3: output = hidden @ W_out^T + b_out
    if (do_output) {
        dim3 grid(DOUT / 128, M / 128);
        gemm_tf32_nt<true><<<grid, 256>>>(hidden_ptr, W_out, b_out, out_ptr, M, DOUT, DH);
    }
}